// round 13
// baseline (speedup 1.0000x reference)
#include <cuda_runtime.h>

// Problem constants
#define BATCH 8
#define CH    256
#define CR    32
#define NPIX  4096   // 64*64

// ---------------------------------------------------------------------------
// Scratch (allocation-free rule: __device__ globals)
// ---------------------------------------------------------------------------
__device__ float g_KT[BATCH * NPIX * CR];                 // keys    [b][n][32]  (w1 proj)
__device__ float g_QT[BATCH * NPIX * CR];                 // queries [b][n][32]  (w2 proj)
__device__ float g_HV[BATCH * CH * NPIX];                 // values  [b][c][n]   (w3 proj)
__device__ float g_P[(size_t)BATCH * NPIX * NPIX];        // scores/probs [b][q][k]  (512 MB)

// ---------------------------------------------------------------------------
// Kernel 1: fused 1x1-conv projections.
// Per block: one batch, 64 spatial columns, all 320 output channels
// (32 keys + 32 queries + 256 values), chunked 64 outputs at a time.
// dyn smem: xs[256][64] + ws[256][64] = 128 KB.
// ---------------------------------------------------------------------------
__global__ void proj_kernel(const float* __restrict__ x,
                            const float* __restrict__ w1,
                            const float* __restrict__ w2,
                            const float* __restrict__ w3) {
    extern __shared__ float sm[];
    float* xs = sm;               // [c][64]  (n contiguous)
    float* ws = sm + 256 * 64;    // [c][64]  (o contiguous, transposed weights)

    const int b   = blockIdx.y;
    const int n0  = blockIdx.x * 64;
    const int tid = threadIdx.x;
    const int tx  = tid & 15;     // n group
    const int ty  = tid >> 4;     // o group

    // Load x tile: [256 c][64 n], coalesced float4 along n.
    const float4* x4  = (const float4*)(x + (size_t)b * CH * NPIX);
    float4*       xs4 = (float4*)xs;
    #pragma unroll
    for (int i = tid; i < 256 * 16; i += 256) {
        int c = i >> 4, f = i & 15;
        xs4[c * 16 + f] = x4[(size_t)c * (NPIX / 4) + (n0 >> 2) + f];
    }

    for (int ch = 0; ch < 5; ch++) {
        __syncthreads();  // protects ws rewrite (and xs on first iter)

        // Load 64 weight rows for this chunk, transposed into ws[c][o].
        for (int i = tid; i < 64 * 64; i += 256) {
            int o  = i >> 6;      // 0..63 local output
            int c4 = i & 63;      // float4 index over c
            const float* wsrc;
            if (ch == 0) wsrc = (o < 32) ? (w1 + o * CH) : (w2 + (o - 32) * CH);
            else         wsrc = w3 + ((ch - 1) * 64 + o) * CH;
            float4 v = ((const float4*)wsrc)[c4];
            int c = c4 * 4;
            ws[(c + 0) * 64 + o] = v.x;
            ws[(c + 1) * 64 + o] = v.y;
            ws[(c + 2) * 64 + o] = v.z;
            ws[(c + 3) * 64 + o] = v.w;
        }
        __syncthreads();

        float acc[4][4];
        #pragma unroll
        for (int i = 0; i < 4; i++)
            #pragma unroll
            for (int j = 0; j < 4; j++) acc[i][j] = 0.0f;

        const float4* ws4 = (const float4*)ws;
        #pragma unroll 8
        for (int c = 0; c < 256; c++) {
            float4 wv = ws4[c * 16 + ty];
            float4 xv = xs4[c * 16 + tx];
            float wa[4] = {wv.x, wv.y, wv.z, wv.w};
            float xa[4] = {xv.x, xv.y, xv.z, xv.w};
            #pragma unroll
            for (int i = 0; i < 4; i++)
                #pragma unroll
                for (int j = 0; j < 4; j++)
                    acc[i][j] = fmaf(wa[i], xa[j], acc[i][j]);
        }

        if (ch == 0) {
            // o_local in [0,32) -> keys (w1/f); [32,64) -> queries (w2/g)
            #pragma unroll
            for (int j = 0; j < 4; j++) {
                int n = n0 + tx * 4 + j;
                float4 v = make_float4(acc[0][j], acc[1][j], acc[2][j], acc[3][j]);
                if (ty < 8) {
                    ((float4*)g_KT)[(((size_t)b * NPIX + n) * CR + ty * 4) >> 2] = v;
                } else {
                    ((float4*)g_QT)[(((size_t)b * NPIX + n) * CR + (ty - 8) * 4) >> 2] = v;
                }
            }
        } else {
            #pragma unroll
            for (int i = 0; i < 4; i++) {
                int o = (ch - 1) * 64 + ty * 4 + i;
                float4 v = make_float4(acc[i][0], acc[i][1], acc[i][2], acc[i][3]);
                ((float4*)g_HV)[(((size_t)b * CH + o) * NPIX + n0 + tx * 4) >> 2] = v;
            }
        }
    }
}

// ---------------------------------------------------------------------------
// Kernel 2: score logits P[b][q][k] = sum_d QT[b][q][d] * KT[b][k][d]
// 64x64 output tile per block, K-dim = 32. Store-bound (writes 512 MB).
// ---------------------------------------------------------------------------
__global__ void score_kernel() {
    __shared__ float qs[32 * 64];  // [d][q]
    __shared__ float ks[32 * 64];  // [d][k]

    const int b   = blockIdx.z;
    const int q0  = blockIdx.y * 64;
    const int k0  = blockIdx.x * 64;
    const int tid = threadIdx.x;
    const int tx  = tid & 15;
    const int ty  = tid >> 4;

    const float4* QT4 = (const float4*)(g_QT + ((size_t)b * NPIX + q0) * CR);
    const float4* KT4 = (const float4*)(g_KT + ((size_t)b * NPIX + k0) * CR);

    #pragma unroll
    for (int i = tid; i < 64 * 8; i += 256) {
        int q = i >> 3, d4 = i & 7;
        float4 v = QT4[q * 8 + d4];
        float4 u = KT4[q * 8 + d4];
        int d = d4 * 4;
        qs[(d + 0) * 64 + q] = v.x; qs[(d + 1) * 64 + q] = v.y;
        qs[(d + 2) * 64 + q] = v.z; qs[(d + 3) * 64 + q] = v.w;
        ks[(d + 0) * 64 + q] = u.x; ks[(d + 1) * 64 + q] = u.y;
        ks[(d + 2) * 64 + q] = u.z; ks[(d + 3) * 64 + q] = u.w;
    }
    __syncthreads();

    float acc[4][4];
    #pragma unroll
    for (int i = 0; i < 4; i++)
        #pragma unroll
        for (int j = 0; j < 4; j++) acc[i][j] = 0.0f;

    const float4* qs4 = (const float4*)qs;
    const float4* ks4 = (const float4*)ks;
    #pragma unroll
    for (int d = 0; d < 32; d++) {
        float4 qv = qs4[d * 16 + ty];
        float4 kv = ks4[d * 16 + tx];
        float qa[4] = {qv.x, qv.y, qv.z, qv.w};
        float ka[4] = {kv.x, kv.y, kv.z, kv.w};
        #pragma unroll
        for (int i = 0; i < 4; i++)
            #pragma unroll
            for (int j = 0; j < 4; j++)
                acc[i][j] = fmaf(qa[i], ka[j], acc[i][j]);
    }

    #pragma unroll
    for (int i = 0; i < 4; i++) {
        size_t q = (size_t)q0 + ty * 4 + i;
        float4 v = make_float4(acc[i][0], acc[i][1], acc[i][2], acc[i][3]);
        ((float4*)g_P)[((((size_t)b * NPIX + q) * NPIX) + k0 + tx * 4) >> 2] = v;
    }
}

// ---------------------------------------------------------------------------
// Kernel 3: softmax over the key dim (contiguous last dim of g_P).
// One block per row; row lives in registers (16 floats/thread).
// ---------------------------------------------------------------------------
__device__ __forceinline__ float warpMax(float v) {
    #pragma unroll
    for (int o = 16; o; o >>= 1) v = fmaxf(v, __shfl_xor_sync(0xffffffffu, v, o));
    return v;
}
__device__ __forceinline__ float warpSum(float v) {
    #pragma unroll
    for (int o = 16; o; o >>= 1) v += __shfl_xor_sync(0xffffffffu, v, o);
    return v;
}

__global__ void softmax_kernel() {
    const size_t row = blockIdx.x;  // b*4096 + q
    float4* r4 = ((float4*)g_P) + row * (NPIX / 4);
    const int tid  = threadIdx.x;
    const int lane = tid & 31, wid = tid >> 5;
    __shared__ float red[8];

    float4 v[4];
    #pragma unroll
    for (int i = 0; i < 4; i++) v[i] = r4[tid + 256 * i];

    float m = -1e30f;
    #pragma unroll
    for (int i = 0; i < 4; i++) {
        m = fmaxf(m, fmaxf(fmaxf(v[i].x, v[i].y), fmaxf(v[i].z, v[i].w)));
    }
    m = warpMax(m);
    if (!lane) red[wid] = m;
    __syncthreads();
    if (tid < 32) {
        float t = (lane < 8) ? red[lane] : -1e30f;
        t = warpMax(t);
        if (!lane) red[0] = t;
    }
    __syncthreads();
    m = red[0];
    __syncthreads();  // all reads of red[0] done before reuse

    float s = 0.0f;
    #pragma unroll
    for (int i = 0; i < 4; i++) {
        v[i].x = __expf(v[i].x - m); v[i].y = __expf(v[i].y - m);
        v[i].z = __expf(v[i].z - m); v[i].w = __expf(v[i].w - m);
        s += (v[i].x + v[i].y) + (v[i].z + v[i].w);
    }
    s = warpSum(s);
    if (!lane) red[wid] = s;
    __syncthreads();
    if (tid < 32) {
        float t = (lane < 8) ? red[lane] : 0.0f;
        t = warpSum(t);
        if (!lane) red[0] = t;
    }
    __syncthreads();
    const float inv = 1.0f / red[0];

    #pragma unroll
    for (int i = 0; i < 4; i++) {
        v[i].x *= inv; v[i].y *= inv; v[i].z *= inv; v[i].w *= inv;
        r4[tid + 256 * i] = v[i];
    }
}

// ---------------------------------------------------------------------------
// Kernel 4: out[b][c][n] = sum_k HV[b][c][k] * P[b][n][k] + x[b][c][n]
// NT SGEMM, 128x128x16 tiles, 8x8 micro-tiles, double-buffered smem.
// ---------------------------------------------------------------------------
__global__ void __launch_bounds__(256, 2)
pv_kernel(const float* __restrict__ x, float* __restrict__ out) {
    __shared__ float As[2][16][128];  // [buf][kk][c]
    __shared__ float Bs[2][16][128];  // [buf][kk][n]

    const int b   = blockIdx.z;
    const int c0  = blockIdx.y * 128;
    const int n0  = blockIdx.x * 128;
    const int tid = threadIdx.x;
    const int tx  = tid & 15;   // n group
    const int ty  = tid >> 4;   // c group

    const float* A  = g_HV + (size_t)b * CH * NPIX;       // [256][4096]
    const float* Bm = g_P  + (size_t)b * NPIX * NPIX;     // [4096][4096]

    const int r0 = tid >> 2,           kc0 = tid & 3;
    const int r1 = (tid + 256) >> 2,   kc1 = (tid + 256) & 3;

    float acc[8][8];
    #pragma unroll
    for (int i = 0; i < 8; i++)
        #pragma unroll
        for (int j = 0; j < 8; j++) acc[i][j] = 0.0f;

    float4 ar0, ar1, br0, br1;

    // prologue: load k-tile 0
    {
        const size_t ka = (size_t)0;
        ar0 = *(const float4*)(A  + (size_t)(c0 + r0) * NPIX + ka + kc0 * 4);
        ar1 = *(const float4*)(A  + (size_t)(c0 + r1) * NPIX + ka + kc1 * 4);
        br0 = *(const float4*)(Bm + (size_t)(n0 + r0) * NPIX + ka + kc0 * 4);
        br1 = *(const float4*)(Bm + (size_t)(n0 + r1) * NPIX + ka + kc1 * 4);
    }

    #pragma unroll 1
    for (int kt = 0; kt < NPIX / 16; kt++) {
        const int buf = kt & 1;

        // stage regs -> smem (transposed to [kk][row])
        As[buf][kc0 * 4 + 0][r0] = ar0.x; As[buf][kc0 * 4 + 1][r0] = ar0.y;
        As[buf][kc0 * 4 + 2][r0] = ar0.z; As[buf][kc0 * 4 + 3][r0] = ar0.w;
        As[buf][kc1 * 4 + 0][r1] = ar1.x; As[buf][kc1 * 4 + 1][r1] = ar1.y;
        As[buf][kc1 * 4 + 2][r1] = ar1.z; As[buf][kc1 * 4 + 3][r1] = ar1.w;
        Bs[buf][kc0 * 4 + 0][r0] = br0.x; Bs[buf][kc0 * 4 + 1][r0] = br0.y;
        Bs[buf][kc0 * 4 + 2][r0] = br0.z; Bs[buf][kc0 * 4 + 3][r0] = br0.w;
        Bs[buf][kc1 * 4 + 0][r1] = br1.x; Bs[buf][kc1 * 4 + 1][r1] = br1.y;
        Bs[buf][kc1 * 4 + 2][r1] = br1.z; Bs[buf][kc1 * 4 + 3][r1] = br1.w;
        __syncthreads();

        // prefetch next k-tile into regs while computing this one
        if (kt + 1 < NPIX / 16) {
            const size_t ka = (size_t)(kt + 1) * 16;
            ar0 = *(const float4*)(A  + (size_t)(c0 + r0) * NPIX + ka + kc0 * 4);
            ar1 = *(const float4*)(A  + (size_t)(c0 + r1) * NPIX + ka + kc1 * 4);
            br0 = *(const float4*)(Bm + (size_t)(n0 + r0) * NPIX + ka + kc0 * 4);
            br1 = *(const float4*)(Bm + (size_t)(n0 + r1) * NPIX + ka + kc1 * 4);
        }

        #pragma unroll
        for (int kk = 0; kk < 16; kk++) {
            const float* asrow = &As[buf][kk][0];
            const float* bsrow = &Bs[buf][kk][0];
            float4 a0 = *(const float4*)(asrow + ty * 8);
            float4 a1 = *(const float4*)(asrow + ty * 8 + 4);
            float4 b0 = *(const float4*)(bsrow + tx * 8);
            float4 b1 = *(const float4*)(bsrow + tx * 8 + 4);
            float av[8] = {a0.x, a0.y, a0.z, a0.w, a1.x, a1.y, a1.z, a1.w};
            float bv[8] = {b0.x, b0.y, b0.z, b0.w, b1.x, b1.y, b1.z, b1.w};
            #pragma unroll
            for (int i = 0; i < 8; i++)
                #pragma unroll
                for (int j = 0; j < 8; j++)
                    acc[i][j] = fmaf(av[i], bv[j], acc[i][j]);
        }
        // single barrier per iteration is sufficient with 2 buffers:
        // next iteration writes buf^1, which everyone finished reading
        // before the barrier of the *current* iteration.
        __syncthreads();
    }

    // epilogue: out = acc + x
    const float* xb = x   + (size_t)b * CH * NPIX;
    float*       ob = out + (size_t)b * CH * NPIX;
    #pragma unroll
    for (int i = 0; i < 8; i++) {
        size_t base = (size_t)(c0 + ty * 8 + i) * NPIX + n0 + tx * 8;
        #pragma unroll
        for (int j4 = 0; j4 < 2; j4++) {
            float4 xv = *(const float4*)(xb + base + j4 * 4);
            float4 r;
            r.x = acc[i][j4 * 4 + 0] + xv.x;
            r.y = acc[i][j4 * 4 + 1] + xv.y;
            r.z = acc[i][j4 * 4 + 2] + xv.z;
            r.w = acc[i][j4 * 4 + 3] + xv.w;
            *(float4*)(ob + base + j4 * 4) = r;
        }
    }
}

// ---------------------------------------------------------------------------
// Launch
// ---------------------------------------------------------------------------
extern "C" void kernel_launch(void* const* d_in, const int* in_sizes, int n_in,
                              void* d_out, int out_size) {
    const float* x  = (const float*)d_in[0];
    const float* w1 = (const float*)d_in[1];
    const float* w2 = (const float*)d_in[2];
    const float* w3 = (const float*)d_in[3];
    float* out = (float*)d_out;

    (void)in_sizes; (void)n_in; (void)out_size;

    const int PROJ_SMEM = 2 * 256 * 64 * (int)sizeof(float);  // 128 KB
    cudaFuncSetAttribute(proj_kernel, cudaFuncAttributeMaxDynamicSharedMemorySize, PROJ_SMEM);

    proj_kernel<<<dim3(NPIX / 64, BATCH), 256, PROJ_SMEM>>>(x, w1, w2, w3);
    score_kernel<<<dim3(NPIX / 64, NPIX / 64, BATCH), 256>>>();
    softmax_kernel<<<BATCH * NPIX, 256>>>();
    pv_kernel<<<dim3(NPIX / 128, CH / 128, BATCH), 256>>>(x, out);
}

// round 15
// speedup vs baseline: 2.6604x; 2.6604x over previous
#include <cuda_runtime.h>
#include <cuda_fp16.h>
#include <stdint.h>

// Problem constants
#define BATCH 8
#define CH    256
#define CR    32
#define NPIX  4096   // 64*64

// ---------------------------------------------------------------------------
// Scratch (allocation-free rule: __device__ globals)
// ---------------------------------------------------------------------------
__device__ float  g_KT[BATCH * NPIX * CR];                 // keys    [b][n][32]
__device__ float  g_QT[BATCH * NPIX * CR];                 // queries [b][n][32]
__device__ __half g_HVh[(size_t)BATCH * CH * NPIX];        // values  [b][c][n] fp16
__device__ float  g_P [(size_t)BATCH * NPIX * NPIX];       // logits [b][q][k] fp32
__device__ __half g_Ph[(size_t)BATCH * NPIX * NPIX];       // probs  [b][q][k] fp16

// ---------------------------------------------------------------------------
// Baseline-PTX helpers (no sm_103a-gated instructions!)
// ---------------------------------------------------------------------------
__device__ __forceinline__ uint32_t smem_u32(const void* p) {
    uint32_t a;
    asm("{ .reg .u64 t; cvta.to.shared.u64 t, %1; cvt.u32.u64 %0, t; }"
        : "=r"(a) : "l"(p));
    return a;
}
#define SW128(o) ((o) ^ ((((uint32_t)(o)) >> 3) & 0x70u))

__device__ __forceinline__ void cp_async16(uint32_t dst, const void* src) {
    asm volatile("cp.async.cg.shared.global [%0], [%1], 16;"
                 :: "r"(dst), "l"(src) : "memory");
}
#define CP_COMMIT() asm volatile("cp.async.commit_group;" ::: "memory")
#define CP_WAIT(n)  asm volatile("cp.async.wait_group %0;" :: "n"(n) : "memory")

__device__ __forceinline__ void ldsm_x4(uint32_t& r0, uint32_t& r1,
                                        uint32_t& r2, uint32_t& r3,
                                        uint32_t addr) {
    asm volatile("ldmatrix.sync.aligned.m8n8.x4.shared.b16 {%0,%1,%2,%3}, [%4];"
                 : "=r"(r0), "=r"(r1), "=r"(r2), "=r"(r3) : "r"(addr));
}
__device__ __forceinline__ void mma16816(float* c,
                                         uint32_t a0, uint32_t a1, uint32_t a2, uint32_t a3,
                                         uint32_t b0, uint32_t b1) {
    asm volatile(
        "mma.sync.aligned.m16n8k16.row.col.f32.f16.f16.f32 "
        "{%0,%1,%2,%3}, {%4,%5,%6,%7}, {%8,%9}, {%0,%1,%2,%3};"
        : "+f"(c[0]), "+f"(c[1]), "+f"(c[2]), "+f"(c[3])
        : "r"(a0), "r"(a1), "r"(a2), "r"(a3), "r"(b0), "r"(b1));
}

// ---------------------------------------------------------------------------
// Kernel 1: fused 1x1-conv projections (fp32 math; HV stored fp16).
// ---------------------------------------------------------------------------
__global__ void proj_kernel(const float* __restrict__ x,
                            const float* __restrict__ w1,
                            const float* __restrict__ w2,
                            const float* __restrict__ w3) {
    extern __shared__ float sm[];
    float* xs = sm;               // [c][64]
    float* ws = sm + 256 * 64;    // [c][64]

    const int b   = blockIdx.y;
    const int n0  = blockIdx.x * 64;
    const int tid = threadIdx.x;
    const int tx  = tid & 15;
    const int ty  = tid >> 4;

    const float4* x4  = (const float4*)(x + (size_t)b * CH * NPIX);
    float4*       xs4 = (float4*)xs;
    #pragma unroll
    for (int i = tid; i < 256 * 16; i += 256) {
        int c = i >> 4, f = i & 15;
        xs4[c * 16 + f] = x4[(size_t)c * (NPIX / 4) + (n0 >> 2) + f];
    }

    for (int ch = 0; ch < 5; ch++) {
        __syncthreads();

        for (int i = tid; i < 64 * 64; i += 256) {
            int o  = i >> 6;
            int c4 = i & 63;
            const float* wsrc;
            if (ch == 0) wsrc = (o < 32) ? (w1 + o * CH) : (w2 + (o - 32) * CH);
            else         wsrc = w3 + ((ch - 1) * 64 + o) * CH;
            float4 v = ((const float4*)wsrc)[c4];
            int c = c4 * 4;
            ws[(c + 0) * 64 + o] = v.x;
            ws[(c + 1) * 64 + o] = v.y;
            ws[(c + 2) * 64 + o] = v.z;
            ws[(c + 3) * 64 + o] = v.w;
        }
        __syncthreads();

        float acc[4][4];
        #pragma unroll
        for (int i = 0; i < 4; i++)
            #pragma unroll
            for (int j = 0; j < 4; j++) acc[i][j] = 0.0f;

        const float4* ws4 = (const float4*)ws;
        #pragma unroll 8
        for (int c = 0; c < 256; c++) {
            float4 wv = ws4[c * 16 + ty];
            float4 xv = xs4[c * 16 + tx];
            float wa[4] = {wv.x, wv.y, wv.z, wv.w};
            float xa[4] = {xv.x, xv.y, xv.z, xv.w};
            #pragma unroll
            for (int i = 0; i < 4; i++)
                #pragma unroll
                for (int j = 0; j < 4; j++)
                    acc[i][j] = fmaf(wa[i], xa[j], acc[i][j]);
        }

        if (ch == 0) {
            #pragma unroll
            for (int j = 0; j < 4; j++) {
                int n = n0 + tx * 4 + j;
                float4 v = make_float4(acc[0][j], acc[1][j], acc[2][j], acc[3][j]);
                if (ty < 8) {
                    ((float4*)g_KT)[(((size_t)b * NPIX + n) * CR + ty * 4) >> 2] = v;
                } else {
                    ((float4*)g_QT)[(((size_t)b * NPIX + n) * CR + (ty - 8) * 4) >> 2] = v;
                }
            }
        } else {
            #pragma unroll
            for (int i = 0; i < 4; i++) {
                int o = (ch - 1) * 64 + ty * 4 + i;
                __half2 lo = __floats2half2_rn(acc[i][0], acc[i][1]);
                __half2 hi = __floats2half2_rn(acc[i][2], acc[i][3]);
                uint2 pv;
                pv.x = *reinterpret_cast<unsigned*>(&lo);
                pv.y = *reinterpret_cast<unsigned*>(&hi);
                *(uint2*)(g_HVh + ((size_t)b * CH + o) * NPIX + n0 + tx * 4) = pv;
            }
        }
    }
}

// ---------------------------------------------------------------------------
// Kernel 2: score logits P[b][q][k] (fp32)
// ---------------------------------------------------------------------------
__global__ void score_kernel() {
    __shared__ float qs[32 * 64];
    __shared__ float ks[32 * 64];

    const int b   = blockIdx.z;
    const int q0  = blockIdx.y * 64;
    const int k0  = blockIdx.x * 64;
    const int tid = threadIdx.x;
    const int tx  = tid & 15;
    const int ty  = tid >> 4;

    const float4* QT4 = (const float4*)(g_QT + ((size_t)b * NPIX + q0) * CR);
    const float4* KT4 = (const float4*)(g_KT + ((size_t)b * NPIX + k0) * CR);

    #pragma unroll
    for (int i = tid; i < 64 * 8; i += 256) {
        int q = i >> 3, d4 = i & 7;
        float4 v = QT4[q * 8 + d4];
        float4 u = KT4[q * 8 + d4];
        int d = d4 * 4;
        qs[(d + 0) * 64 + q] = v.x; qs[(d + 1) * 64 + q] = v.y;
        qs[(d + 2) * 64 + q] = v.z; qs[(d + 3) * 64 + q] = v.w;
        ks[(d + 0) * 64 + q] = u.x; ks[(d + 1) * 64 + q] = u.y;
        ks[(d + 2) * 64 + q] = u.z; ks[(d + 3) * 64 + q] = u.w;
    }
    __syncthreads();

    float acc[4][4];
    #pragma unroll
    for (int i = 0; i < 4; i++)
        #pragma unroll
        for (int j = 0; j < 4; j++) acc[i][j] = 0.0f;

    const float4* qs4 = (const float4*)qs;
    const float4* ks4 = (const float4*)ks;
    #pragma unroll
    for (int d = 0; d < 32; d++) {
        float4 qv = qs4[d * 16 + ty];
        float4 kv = ks4[d * 16 + tx];
        float qa[4] = {qv.x, qv.y, qv.z, qv.w};
        float ka[4] = {kv.x, kv.y, kv.z, kv.w};
        #pragma unroll
        for (int i = 0; i < 4; i++)
            #pragma unroll
            for (int j = 0; j < 4; j++)
                acc[i][j] = fmaf(qa[i], ka[j], acc[i][j]);
    }

    #pragma unroll
    for (int i = 0; i < 4; i++) {
        size_t q = (size_t)q0 + ty * 4 + i;
        float4 v = make_float4(acc[i][0], acc[i][1], acc[i][2], acc[i][3]);
        ((float4*)g_P)[((((size_t)b * NPIX + q) * NPIX) + k0 + tx * 4) >> 2] = v;
    }
}

// ---------------------------------------------------------------------------
// Kernel 3: softmax over k (fp32 in, fp16 out)
// ---------------------------------------------------------------------------
__device__ __forceinline__ float warpMax(float v) {
    #pragma unroll
    for (int o = 16; o; o >>= 1) v = fmaxf(v, __shfl_xor_sync(0xffffffffu, v, o));
    return v;
}
__device__ __forceinline__ float warpSum(float v) {
    #pragma unroll
    for (int o = 16; o; o >>= 1) v += __shfl_xor_sync(0xffffffffu, v, o);
    return v;
}

__global__ void softmax_kernel() {
    const size_t row = blockIdx.x;  // b*4096 + q
    const float4* r4 = ((const float4*)g_P) + row * (NPIX / 4);
    __half* dst = g_Ph + row * NPIX;
    const int tid  = threadIdx.x;
    const int lane = tid & 31, wid = tid >> 5;
    __shared__ float red[8];

    float4 v[4];
    #pragma unroll
    for (int i = 0; i < 4; i++) v[i] = r4[tid + 256 * i];

    float m = -1e30f;
    #pragma unroll
    for (int i = 0; i < 4; i++)
        m = fmaxf(m, fmaxf(fmaxf(v[i].x, v[i].y), fmaxf(v[i].z, v[i].w)));
    m = warpMax(m);
    if (!lane) red[wid] = m;
    __syncthreads();
    if (tid < 32) {
        float t = (lane < 8) ? red[lane] : -1e30f;
        t = warpMax(t);
        if (!lane) red[0] = t;
    }
    __syncthreads();
    m = red[0];
    __syncthreads();

    float s = 0.0f;
    #pragma unroll
    for (int i = 0; i < 4; i++) {
        v[i].x = __expf(v[i].x - m); v[i].y = __expf(v[i].y - m);
        v[i].z = __expf(v[i].z - m); v[i].w = __expf(v[i].w - m);
        s += (v[i].x + v[i].y) + (v[i].z + v[i].w);
    }
    s = warpSum(s);
    if (!lane) red[wid] = s;
    __syncthreads();
    if (tid < 32) {
        float t = (lane < 8) ? red[lane] : 0.0f;
        t = warpSum(t);
        if (!lane) red[0] = t;
    }
    __syncthreads();
    const float inv = 1.0f / red[0];

    #pragma unroll
    for (int i = 0; i < 4; i++) {
        __half2 p0 = __floats2half2_rn(v[i].x * inv, v[i].y * inv);
        __half2 p1 = __floats2half2_rn(v[i].z * inv, v[i].w * inv);
        uint2 w;
        w.x = *reinterpret_cast<unsigned*>(&p0);
        w.y = *reinterpret_cast<unsigned*>(&p1);
        *(uint2*)(dst + (size_t)(tid + 256 * i) * 4) = w;
    }
}

// ---------------------------------------------------------------------------
// Kernel 4: PV via warp-level tensor cores (mma.sync m16n8k16 fp16 -> fp32).
// out[b][c][n] = sum_k HVh[b][c][k] * Ph[b][n][k] + x[b][c][n]
// CTA tile M(c)=128, N(n)=128, K-tile=64 halfs (SW128 smem), 256 threads,
// 8 warps as 2(m) x 4(n), warp tile 64x32. cp.async double-buffered.
// ---------------------------------------------------------------------------
#define PV_KT    64
#define PV_NT    (NPIX / PV_KT)           // 64 k-tiles
#define PV_TILEB 16384                    // 128 rows x 128 bytes
#define PV_BUFB  (2 * PV_TILEB)           // A + B per stage

__global__ void __launch_bounds__(256)
pv_mma_kernel(const float* __restrict__ x, float* __restrict__ out) {
    extern __shared__ __align__(1024) unsigned char dynsm[];  // 2 stages x 32 KB

    const int b    = blockIdx.z;
    const int c0   = blockIdx.y * 128;
    const int n0   = blockIdx.x * 128;
    const int tid  = threadIdx.x;
    const int lane = tid & 31;
    const int wid  = tid >> 5;
    const int wm   = wid >> 2;   // 0..1 : 64 rows (c)
    const int wn   = wid & 3;    // 0..3 : 32 cols (n)

    const __half* Ab = g_HVh + ((size_t)b * CH   + c0) * NPIX;
    const __half* Bb = g_Ph  + ((size_t)b * NPIX + n0) * NPIX;

    const uint32_t sm_base = smem_u32(dynsm);

    // loader: 4 chunks of A + 4 of B per thread per tile (16B each)
    const int lrow = tid >> 3;         // +32 per j
    const int lkc  = tid & 7;

    float acc[4][4][4];
    #pragma unroll
    for (int i = 0; i < 4; i++)
        #pragma unroll
        for (int j = 0; j < 4; j++)
            #pragma unroll
            for (int q = 0; q < 4; q++) acc[i][j][q] = 0.0f;

    // ldmatrix lane addressing (within-tile byte offsets, pre-swizzle)
    const int a_row = wm * 64 + (lane & 15);             // + mf*16
    const int a_kb  = (lane >> 4) * 16;                  // + ks*32 (bytes)
    const int b_row = wn * 32 + (lane & 7) + ((lane >> 4) & 1) * 8;  // + nh*16
    const int b_kb  = ((lane >> 3) & 1) * 16;            // + ks*32 (bytes)

    // ---- prologue: stage tile 0
    {
        uint32_t sA = sm_base;
        uint32_t sB = sm_base + PV_TILEB;
        #pragma unroll
        for (int j = 0; j < 4; j++) {
            int row = lrow + 32 * j;
            uint32_t soff = SW128((uint32_t)(row * 128 + lkc * 16));
            cp_async16(sA + soff, Ab + (size_t)row * NPIX + lkc * 8);
            cp_async16(sB + soff, Bb + (size_t)row * NPIX + lkc * 8);
        }
        CP_COMMIT();
    }

    #pragma unroll 1
    for (int kt = 0; kt < PV_NT; kt++) {
        const int buf = kt & 1;
        const uint32_t sA = sm_base + buf * PV_BUFB;
        const uint32_t sB = sA + PV_TILEB;

        if (kt + 1 < PV_NT) {
            const uint32_t dA = sm_base + (buf ^ 1) * PV_BUFB;
            const uint32_t dB = dA + PV_TILEB;
            const size_t kofs = (size_t)(kt + 1) * PV_KT;
            #pragma unroll
            for (int j = 0; j < 4; j++) {
                int row = lrow + 32 * j;
                uint32_t soff = SW128((uint32_t)(row * 128 + lkc * 16));
                cp_async16(dA + soff, Ab + (size_t)row * NPIX + kofs + lkc * 8);
                cp_async16(dB + soff, Bb + (size_t)row * NPIX + kofs + lkc * 8);
            }
            CP_COMMIT();
            CP_WAIT(1);
        } else {
            CP_WAIT(0);
        }
        __syncthreads();

        #pragma unroll
        for (int ks = 0; ks < 4; ks++) {
            uint32_t af[4][4];
            #pragma unroll
            for (int mf = 0; mf < 4; mf++) {
                uint32_t off = (uint32_t)((a_row + mf * 16) * 128 + ks * 32 + a_kb);
                ldsm_x4(af[mf][0], af[mf][1], af[mf][2], af[mf][3], sA + SW128(off));
            }
            uint32_t bf[2][4];
            #pragma unroll
            for (int nh = 0; nh < 2; nh++) {
                uint32_t off = (uint32_t)((b_row + nh * 16) * 128 + ks * 32 + b_kb);
                ldsm_x4(bf[nh][0], bf[nh][1], bf[nh][2], bf[nh][3], sB + SW128(off));
            }
            #pragma unroll
            for (int mf = 0; mf < 4; mf++)
                #pragma unroll
                for (int nf = 0; nf < 4; nf++)
                    mma16816(acc[mf][nf],
                             af[mf][0], af[mf][1], af[mf][2], af[mf][3],
                             bf[nf >> 1][(nf & 1) * 2], bf[nf >> 1][(nf & 1) * 2 + 1]);
        }
        __syncthreads();
    }

    // ---- epilogue: out = acc + x  (float2 stores, 32B per quarter-warp)
    const float* xb = x   + (size_t)b * CH * NPIX;
    float*       ob = out + (size_t)b * CH * NPIX;
    const int g = lane >> 2, t = lane & 3;

    #pragma unroll
    for (int mf = 0; mf < 4; mf++) {
        const int r0 = c0 + wm * 64 + mf * 16 + g;
        #pragma unroll
        for (int nf = 0; nf < 4; nf++) {
            const int col = n0 + wn * 32 + nf * 8 + 2 * t;
            size_t i0 = (size_t)r0 * NPIX + col;
            size_t i1 = (size_t)(r0 + 8) * NPIX + col;
            float2 x0 = *(const float2*)(xb + i0);
            float2 x1 = *(const float2*)(xb + i1);
            float2 o0 = make_float2(acc[mf][nf][0] + x0.x, acc[mf][nf][1] + x0.y);
            float2 o1 = make_float2(acc[mf][nf][2] + x1.x, acc[mf][nf][3] + x1.y);
            *(float2*)(ob + i0) = o0;
            *(float2*)(ob + i1) = o1;
        }
    }
}

// ---------------------------------------------------------------------------
// Launch
// ---------------------------------------------------------------------------
extern "C" void kernel_launch(void* const* d_in, const int* in_sizes, int n_in,
                              void* d_out, int out_size) {
    const float* x  = (const float*)d_in[0];
    const float* w1 = (const float*)d_in[1];
    const float* w2 = (const float*)d_in[2];
    const float* w3 = (const float*)d_in[3];
    float* out = (float*)d_out;

    (void)in_sizes; (void)n_in; (void)out_size;

    const int PROJ_SMEM = 2 * 256 * 64 * (int)sizeof(float);  // 128 KB
    cudaFuncSetAttribute(proj_kernel, cudaFuncAttributeMaxDynamicSharedMemorySize, PROJ_SMEM);
    const int PV_SMEM = 2 * PV_BUFB;  // 64 KB
    cudaFuncSetAttribute(pv_mma_kernel, cudaFuncAttributeMaxDynamicSharedMemorySize, PV_SMEM);

    proj_kernel<<<dim3(NPIX / 64, BATCH), 256, PROJ_SMEM>>>(x, w1, w2, w3);
    score_kernel<<<dim3(NPIX / 64, NPIX / 64, BATCH), 256>>>();
    softmax_kernel<<<BATCH * NPIX, 256>>>();
    pv_mma_kernel<<<dim3(NPIX / 128, CH / 128, BATCH), 256, PV_SMEM>>>(x, out);
}

// round 16
// speedup vs baseline: 2.6622x; 1.0007x over previous
#include <cuda_runtime.h>
#include <cuda_fp16.h>
#include <stdint.h>

// Problem constants
#define BATCH 8
#define CH    256
#define CR    32
#define NPIX  4096   // 64*64

// ---------------------------------------------------------------------------
// Scratch (allocation-free rule: __device__ globals)
// ---------------------------------------------------------------------------
__device__ float  g_KT[BATCH * NPIX * CR];                 // keys    [b][n][32]
__device__ float  g_QT[BATCH * NPIX * CR];                 // queries [b][n][32]
__device__ __half g_HVh[(size_t)BATCH * CH * NPIX];        // values  [b][c][n] fp16
__device__ float  g_P [(size_t)BATCH * NPIX * NPIX];       // logits [b][q][k] fp32
__device__ __half g_Ph[(size_t)BATCH * NPIX * NPIX];       // probs  [b][q][k] fp16

// ---------------------------------------------------------------------------
// Baseline-PTX helpers (no sm_103a-gated instructions!)
// ---------------------------------------------------------------------------
__device__ __forceinline__ uint32_t smem_u32(const void* p) {
    uint32_t a;
    asm("{ .reg .u64 t; cvta.to.shared.u64 t, %1; cvt.u32.u64 %0, t; }"
        : "=r"(a) : "l"(p));
    return a;
}
#define SW128(o) ((o) ^ ((((uint32_t)(o)) >> 3) & 0x70u))

__device__ __forceinline__ void cp_async16(uint32_t dst, const void* src) {
    asm volatile("cp.async.cg.shared.global [%0], [%1], 16;"
                 :: "r"(dst), "l"(src) : "memory");
}
#define CP_COMMIT() asm volatile("cp.async.commit_group;" ::: "memory")
#define CP_WAIT(n)  asm volatile("cp.async.wait_group %0;" :: "n"(n) : "memory")

__device__ __forceinline__ void ldsm_x4(uint32_t& r0, uint32_t& r1,
                                        uint32_t& r2, uint32_t& r3,
                                        uint32_t addr) {
    asm volatile("ldmatrix.sync.aligned.m8n8.x4.shared.b16 {%0,%1,%2,%3}, [%4];"
                 : "=r"(r0), "=r"(r1), "=r"(r2), "=r"(r3) : "r"(addr));
}
__device__ __forceinline__ void mma16816(float* c,
                                         uint32_t a0, uint32_t a1, uint32_t a2, uint32_t a3,
                                         uint32_t b0, uint32_t b1) {
    asm volatile(
        "mma.sync.aligned.m16n8k16.row.col.f32.f16.f16.f32 "
        "{%0,%1,%2,%3}, {%4,%5,%6,%7}, {%8,%9}, {%0,%1,%2,%3};"
        : "+f"(c[0]), "+f"(c[1]), "+f"(c[2]), "+f"(c[3])
        : "r"(a0), "r"(a1), "r"(a2), "r"(a3), "r"(b0), "r"(b1));
}

// ---------------------------------------------------------------------------
// Kernel 1: fused 1x1-conv projections (fp32 math; HV stored fp16).
// ---------------------------------------------------------------------------
__global__ void proj_kernel(const float* __restrict__ x,
                            const float* __restrict__ w1,
                            const float* __restrict__ w2,
                            const float* __restrict__ w3) {
    extern __shared__ float sm[];
    float* xs = sm;               // [c][64]
    float* ws = sm + 256 * 64;    // [c][64]

    const int b   = blockIdx.y;
    const int n0  = blockIdx.x * 64;
    const int tid = threadIdx.x;
    const int tx  = tid & 15;
    const int ty  = tid >> 4;

    const float4* x4  = (const float4*)(x + (size_t)b * CH * NPIX);
    float4*       xs4 = (float4*)xs;
    #pragma unroll
    for (int i = tid; i < 256 * 16; i += 256) {
        int c = i >> 4, f = i & 15;
        xs4[c * 16 + f] = x4[(size_t)c * (NPIX / 4) + (n0 >> 2) + f];
    }

    for (int ch = 0; ch < 5; ch++) {
        __syncthreads();

        for (int i = tid; i < 64 * 64; i += 256) {
            int o  = i >> 6;
            int c4 = i & 63;
            const float* wsrc;
            if (ch == 0) wsrc = (o < 32) ? (w1 + o * CH) : (w2 + (o - 32) * CH);
            else         wsrc = w3 + ((ch - 1) * 64 + o) * CH;
            float4 v = ((const float4*)wsrc)[c4];
            int c = c4 * 4;
            ws[(c + 0) * 64 + o] = v.x;
            ws[(c + 1) * 64 + o] = v.y;
            ws[(c + 2) * 64 + o] = v.z;
            ws[(c + 3) * 64 + o] = v.w;
        }
        __syncthreads();

        float acc[4][4];
        #pragma unroll
        for (int i = 0; i < 4; i++)
            #pragma unroll
            for (int j = 0; j < 4; j++) acc[i][j] = 0.0f;

        const float4* ws4 = (const float4*)ws;
        #pragma unroll 8
        for (int c = 0; c < 256; c++) {
            float4 wv = ws4[c * 16 + ty];
            float4 xv = xs4[c * 16 + tx];
            float wa[4] = {wv.x, wv.y, wv.z, wv.w};
            float xa[4] = {xv.x, xv.y, xv.z, xv.w};
            #pragma unroll
            for (int i = 0; i < 4; i++)
                #pragma unroll
                for (int j = 0; j < 4; j++)
                    acc[i][j] = fmaf(wa[i], xa[j], acc[i][j]);
        }

        if (ch == 0) {
            #pragma unroll
            for (int j = 0; j < 4; j++) {
                int n = n0 + tx * 4 + j;
                float4 v = make_float4(acc[0][j], acc[1][j], acc[2][j], acc[3][j]);
                if (ty < 8) {
                    ((float4*)g_KT)[(((size_t)b * NPIX + n) * CR + ty * 4) >> 2] = v;
                } else {
                    ((float4*)g_QT)[(((size_t)b * NPIX + n) * CR + (ty - 8) * 4) >> 2] = v;
                }
            }
        } else {
            #pragma unroll
            for (int i = 0; i < 4; i++) {
                int o = (ch - 1) * 64 + ty * 4 + i;
                __half2 lo = __floats2half2_rn(acc[i][0], acc[i][1]);
                __half2 hi = __floats2half2_rn(acc[i][2], acc[i][3]);
                uint2 pv;
                pv.x = *reinterpret_cast<unsigned*>(&lo);
                pv.y = *reinterpret_cast<unsigned*>(&hi);
                *(uint2*)(g_HVh + ((size_t)b * CH + o) * NPIX + n0 + tx * 4) = pv;
            }
        }
    }
}

// ---------------------------------------------------------------------------
// Kernel 2: score logits P[b][q][k] (fp32)
// ---------------------------------------------------------------------------
__global__ void score_kernel() {
    __shared__ float qs[32 * 64];
    __shared__ float ks[32 * 64];

    const int b   = blockIdx.z;
    const int q0  = blockIdx.y * 64;
    const int k0  = blockIdx.x * 64;
    const int tid = threadIdx.x;
    const int tx  = tid & 15;
    const int ty  = tid >> 4;

    const float4* QT4 = (const float4*)(g_QT + ((size_t)b * NPIX + q0) * CR);
    const float4* KT4 = (const float4*)(g_KT + ((size_t)b * NPIX + k0) * CR);

    #pragma unroll
    for (int i = tid; i < 64 * 8; i += 256) {
        int q = i >> 3, d4 = i & 7;
        float4 v = QT4[q * 8 + d4];
        float4 u = KT4[q * 8 + d4];
        int d = d4 * 4;
        qs[(d + 0) * 64 + q] = v.x; qs[(d + 1) * 64 + q] = v.y;
        qs[(d + 2) * 64 + q] = v.z; qs[(d + 3) * 64 + q] = v.w;
        ks[(d + 0) * 64 + q] = u.x; ks[(d + 1) * 64 + q] = u.y;
        ks[(d + 2) * 64 + q] = u.z; ks[(d + 3) * 64 + q] = u.w;
    }
    __syncthreads();

    float acc[4][4];
    #pragma unroll
    for (int i = 0; i < 4; i++)
        #pragma unroll
        for (int j = 0; j < 4; j++) acc[i][j] = 0.0f;

    const float4* qs4 = (const float4*)qs;
    const float4* ks4 = (const float4*)ks;
    #pragma unroll
    for (int d = 0; d < 32; d++) {
        float4 qv = qs4[d * 16 + ty];
        float4 kv = ks4[d * 16 + tx];
        float qa[4] = {qv.x, qv.y, qv.z, qv.w};
        float ka[4] = {kv.x, kv.y, kv.z, kv.w};
        #pragma unroll
        for (int i = 0; i < 4; i++)
            #pragma unroll
            for (int j = 0; j < 4; j++)
                acc[i][j] = fmaf(qa[i], ka[j], acc[i][j]);
    }

    #pragma unroll
    for (int i = 0; i < 4; i++) {
        size_t q = (size_t)q0 + ty * 4 + i;
        float4 v = make_float4(acc[i][0], acc[i][1], acc[i][2], acc[i][3]);
        ((float4*)g_P)[((((size_t)b * NPIX + q) * NPIX) + k0 + tx * 4) >> 2] = v;
    }
}

// ---------------------------------------------------------------------------
// Kernel 3: softmax over k (fp32 in, fp16 out)
// ---------------------------------------------------------------------------
__device__ __forceinline__ float warpMax(float v) {
    #pragma unroll
    for (int o = 16; o; o >>= 1) v = fmaxf(v, __shfl_xor_sync(0xffffffffu, v, o));
    return v;
}
__device__ __forceinline__ float warpSum(float v) {
    #pragma unroll
    for (int o = 16; o; o >>= 1) v += __shfl_xor_sync(0xffffffffu, v, o);
    return v;
}

__global__ void softmax_kernel() {
    const size_t row = blockIdx.x;  // b*4096 + q
    const float4* r4 = ((const float4*)g_P) + row * (NPIX / 4);
    __half* dst = g_Ph + row * NPIX;
    const int tid  = threadIdx.x;
    const int lane = tid & 31, wid = tid >> 5;
    __shared__ float red[8];

    float4 v[4];
    #pragma unroll
    for (int i = 0; i < 4; i++) v[i] = r4[tid + 256 * i];

    float m = -1e30f;
    #pragma unroll
    for (int i = 0; i < 4; i++)
        m = fmaxf(m, fmaxf(fmaxf(v[i].x, v[i].y), fmaxf(v[i].z, v[i].w)));
    m = warpMax(m);
    if (!lane) red[wid] = m;
    __syncthreads();
    if (tid < 32) {
        float t = (lane < 8) ? red[lane] : -1e30f;
        t = warpMax(t);
        if (!lane) red[0] = t;
    }
    __syncthreads();
    m = red[0];
    __syncthreads();

    float s = 0.0f;
    #pragma unroll
    for (int i = 0; i < 4; i++) {
        v[i].x = __expf(v[i].x - m); v[i].y = __expf(v[i].y - m);
        v[i].z = __expf(v[i].z - m); v[i].w = __expf(v[i].w - m);
        s += (v[i].x + v[i].y) + (v[i].z + v[i].w);
    }
    s = warpSum(s);
    if (!lane) red[wid] = s;
    __syncthreads();
    if (tid < 32) {
        float t = (lane < 8) ? red[lane] : 0.0f;
        t = warpSum(t);
        if (!lane) red[0] = t;
    }
    __syncthreads();
    const float inv = 1.0f / red[0];

    #pragma unroll
    for (int i = 0; i < 4; i++) {
        __half2 p0 = __floats2half2_rn(v[i].x * inv, v[i].y * inv);
        __half2 p1 = __floats2half2_rn(v[i].z * inv, v[i].w * inv);
        uint2 w;
        w.x = *reinterpret_cast<unsigned*>(&p0);
        w.y = *reinterpret_cast<unsigned*>(&p1);
        *(uint2*)(dst + (size_t)(tid + 256 * i) * 4) = w;
    }
}

// ---------------------------------------------------------------------------
// Kernel 4: PV via warp-level tensor cores (mma.sync m16n8k16 fp16 -> fp32).
// out[b][c][n] = sum_k HVh[b][c][k] * Ph[b][n][k] + x[b][c][n]
// CTA tile M(c)=128, N(n)=128, K-tile=64 halfs (SW128 smem), 256 threads,
// 8 warps as 2(m) x 4(n), warp tile 64x32. cp.async double-buffered.
// ---------------------------------------------------------------------------
#define PV_KT    64
#define PV_NT    (NPIX / PV_KT)           // 64 k-tiles
#define PV_TILEB 16384                    // 128 rows x 128 bytes
#define PV_BUFB  (2 * PV_TILEB)           // A + B per stage

__global__ void __launch_bounds__(256)
pv_mma_kernel(const float* __restrict__ x, float* __restrict__ out) {
    extern __shared__ __align__(1024) unsigned char dynsm[];  // 2 stages x 32 KB

    const int b    = blockIdx.z;
    const int c0   = blockIdx.y * 128;
    const int n0   = blockIdx.x * 128;
    const int tid  = threadIdx.x;
    const int lane = tid & 31;
    const int wid  = tid >> 5;
    const int wm   = wid >> 2;   // 0..1 : 64 rows (c)
    const int wn   = wid & 3;    // 0..3 : 32 cols (n)

    const __half* Ab = g_HVh + ((size_t)b * CH   + c0) * NPIX;
    const __half* Bb = g_Ph  + ((size_t)b * NPIX + n0) * NPIX;

    const uint32_t sm_base = smem_u32(dynsm);

    // loader: 4 chunks of A + 4 of B per thread per tile (16B each)
    const int lrow = tid >> 3;         // +32 per j
    const int lkc  = tid & 7;

    float acc[4][4][4];
    #pragma unroll
    for (int i = 0; i < 4; i++)
        #pragma unroll
        for (int j = 0; j < 4; j++)
            #pragma unroll
            for (int q = 0; q < 4; q++) acc[i][j][q] = 0.0f;

    // ldmatrix lane addressing (within-tile byte offsets, pre-swizzle)
    const int a_row = wm * 64 + (lane & 15);             // + mf*16
    const int a_kb  = (lane >> 4) * 16;                  // + ks*32 (bytes)
    const int b_row = wn * 32 + (lane & 7) + ((lane >> 4) & 1) * 8;  // + nh*16
    const int b_kb  = ((lane >> 3) & 1) * 16;            // + ks*32 (bytes)

    // ---- prologue: stage tile 0
    {
        uint32_t sA = sm_base;
        uint32_t sB = sm_base + PV_TILEB;
        #pragma unroll
        for (int j = 0; j < 4; j++) {
            int row = lrow + 32 * j;
            uint32_t soff = SW128((uint32_t)(row * 128 + lkc * 16));
            cp_async16(sA + soff, Ab + (size_t)row * NPIX + lkc * 8);
            cp_async16(sB + soff, Bb + (size_t)row * NPIX + lkc * 8);
        }
        CP_COMMIT();
    }

    #pragma unroll 1
    for (int kt = 0; kt < PV_NT; kt++) {
        const int buf = kt & 1;
        const uint32_t sA = sm_base + buf * PV_BUFB;
        const uint32_t sB = sA + PV_TILEB;

        if (kt + 1 < PV_NT) {
            const uint32_t dA = sm_base + (buf ^ 1) * PV_BUFB;
            const uint32_t dB = dA + PV_TILEB;
            const size_t kofs = (size_t)(kt + 1) * PV_KT;
            #pragma unroll
            for (int j = 0; j < 4; j++) {
                int row = lrow + 32 * j;
                uint32_t soff = SW128((uint32_t)(row * 128 + lkc * 16));
                cp_async16(dA + soff, Ab + (size_t)row * NPIX + kofs + lkc * 8);
                cp_async16(dB + soff, Bb + (size_t)row * NPIX + kofs + lkc * 8);
            }
            CP_COMMIT();
            CP_WAIT(1);
        } else {
            CP_WAIT(0);
        }
        __syncthreads();

        #pragma unroll
        for (int ks = 0; ks < 4; ks++) {
            uint32_t af[4][4];
            #pragma unroll
            for (int mf = 0; mf < 4; mf++) {
                uint32_t off = (uint32_t)((a_row + mf * 16) * 128 + ks * 32 + a_kb);
                ldsm_x4(af[mf][0], af[mf][1], af[mf][2], af[mf][3], sA + SW128(off));
            }
            uint32_t bf[2][4];
            #pragma unroll
            for (int nh = 0; nh < 2; nh++) {
                uint32_t off = (uint32_t)((b_row + nh * 16) * 128 + ks * 32 + b_kb);
                ldsm_x4(bf[nh][0], bf[nh][1], bf[nh][2], bf[nh][3], sB + SW128(off));
            }
            #pragma unroll
            for (int mf = 0; mf < 4; mf++)
                #pragma unroll
                for (int nf = 0; nf < 4; nf++)
                    mma16816(acc[mf][nf],
                             af[mf][0], af[mf][1], af[mf][2], af[mf][3],
                             bf[nf >> 1][(nf & 1) * 2], bf[nf >> 1][(nf & 1) * 2 + 1]);
        }
        __syncthreads();
    }

    // ---- epilogue: out = acc + x  (float2 stores, 32B per quarter-warp)
    const float* xb = x   + (size_t)b * CH * NPIX;
    float*       ob = out + (size_t)b * CH * NPIX;
    const int g = lane >> 2, t = lane & 3;

    #pragma unroll
    for (int mf = 0; mf < 4; mf++) {
        const int r0 = c0 + wm * 64 + mf * 16 + g;
        #pragma unroll
        for (int nf = 0; nf < 4; nf++) {
            const int col = n0 + wn * 32 + nf * 8 + 2 * t;
            size_t i0 = (size_t)r0 * NPIX + col;
            size_t i1 = (size_t)(r0 + 8) * NPIX + col;
            float2 x0 = *(const float2*)(xb + i0);
            float2 x1 = *(const float2*)(xb + i1);
            float2 o0 = make_float2(acc[mf][nf][0] + x0.x, acc[mf][nf][1] + x0.y);
            float2 o1 = make_float2(acc[mf][nf][2] + x1.x, acc[mf][nf][3] + x1.y);
            *(float2*)(ob + i0) = o0;
            *(float2*)(ob + i1) = o1;
        }
    }
}

// ---------------------------------------------------------------------------
// Launch
// ---------------------------------------------------------------------------
extern "C" void kernel_launch(void* const* d_in, const int* in_sizes, int n_in,
                              void* d_out, int out_size) {
    const float* x  = (const float*)d_in[0];
    const float* w1 = (const float*)d_in[1];
    const float* w2 = (const float*)d_in[2];
    const float* w3 = (const float*)d_in[3];
    float* out = (float*)d_out;

    (void)in_sizes; (void)n_in; (void)out_size;

    const int PROJ_SMEM = 2 * 256 * 64 * (int)sizeof(float);  // 128 KB
    cudaFuncSetAttribute(proj_kernel, cudaFuncAttributeMaxDynamicSharedMemorySize, PROJ_SMEM);
    const int PV_SMEM = 2 * PV_BUFB;  // 64 KB
    cudaFuncSetAttribute(pv_mma_kernel, cudaFuncAttributeMaxDynamicSharedMemorySize, PV_SMEM);

    proj_kernel<<<dim3(NPIX / 64, BATCH), 256, PROJ_SMEM>>>(x, w1, w2, w3);
    score_kernel<<<dim3(NPIX / 64, NPIX / 64, BATCH), 256>>>();
    softmax_kernel<<<BATCH * NPIX, 256>>>();
    pv_mma_kernel<<<dim3(NPIX / 128, CH / 128, BATCH), 256, PV_SMEM>>>(x, out);
}